// round 9
// baseline (speedup 1.0000x reference)
#include <cuda_runtime.h>
#include <math.h>
#include <stdint.h>

#define NN 50000
#define NE 400000
#define TE 450000         // NE + NN self loops
#define HID 256
#define BATCHB 16

// ---------------- scratch ----------------
__device__ float g_h [(size_t)NN*HID];   // layer input / LN output
__device__ float g_hp[(size_t)NN*HID];   // h @ W (also feats buffer, N*192 < N*256)
__device__ float g_ssrc[NN*4];
__device__ float g_sdst[NN*4];
__device__ int   g_cnt[NN];
__device__ int   g_rowptr[NN+1];
__device__ int   g_cur[NN];
__device__ int   g_col[TE];
__device__ int   g_part[256];
__device__ float g_pool[BATCHB*HID];
__device__ int   g_bcnt[BATCHB];
__device__ float g_rates[64];

// ---------------- helpers ----------------
__device__ __forceinline__ void cp16p(void* sdst, const void* gsrc, int src_bytes) {
    unsigned sa = (unsigned)__cvta_generic_to_shared(sdst);
    asm volatile("cp.async.cg.shared.global [%0], [%1], 16, %2;"
                 :: "r"(sa), "l"(gsrc), "r"(src_bytes));
}
__device__ __forceinline__ void cp_commit() { asm volatile("cp.async.commit_group;"); }
__device__ __forceinline__ void cp_wait1()  { asm volatile("cp.async.wait_group 1;"); }
__device__ __forceinline__ void cp_wait0()  { asm volatile("cp.async.wait_group 0;"); }
__device__ __forceinline__ void ffma2(unsigned long long& d,
                                      unsigned long long a,
                                      unsigned long long b) {
    asm volatile("fma.rn.f32x2 %0, %1, %2, %0;" : "+l"(d) : "l"(a), "l"(b));
}

// ---------------- init ----------------
__global__ void zero_kernel() {
    int i = blockIdx.x*blockDim.x + threadIdx.x;
    if (i < NN) g_cnt[i] = 0;
    if (i < BATCHB*HID) g_pool[i] = 0.f;
    if (i < BATCHB) g_bcnt[i] = 0;
    if (i == 0) g_rowptr[NN] = TE;
}

__global__ void rates_kernel() {
    int j = threadIdx.x;
    if (j < 64) {
        double e = -(double)(2*(j>>1)) / 64.0;
        g_rates[j] = (float)pow(10000.0, e);
    }
}

// feats = [x | region_emb[rid] | posenc]  -> g_hp as [N,192]
__global__ void feats_kernel(const float* __restrict__ x,
                             const float* __restrict__ remb,
                             const int*   __restrict__ rid) {
    int idx = blockIdx.x*blockDim.x + threadIdx.x;
    if (idx >= NN*48) return;
    int n = idx / 48, q = idx - n*48;
    float4 v;
    if (q < 16)      v = ((const float4*)x)[(size_t)n*16 + q];
    else if (q < 32) v = ((const float4*)remb)[(size_t)rid[n]*16 + (q-16)];
    else {
        int j = (q - 32) * 4;
        float fn = (float)n;
        v.x = sinf(fn * g_rates[j+0]);
        v.y = cosf(fn * g_rates[j+1]);
        v.z = sinf(fn * g_rates[j+2]);
        v.w = cosf(fn * g_rates[j+3]);
    }
    ((float4*)g_hp)[(size_t)n*48 + q] = v;
}

// ---------------- CSR build (dst-major) ----------------
__global__ void count_kernel(const int* __restrict__ ei) {
    int i = blockIdx.x*blockDim.x + threadIdx.x;
    if (i >= TE) return;
    int dst = (i < NE) ? ei[NE + i] : (i - NE);
    atomicAdd(&g_cnt[dst], 1);
}

__global__ void scan1_kernel() {
    __shared__ int s[256];
    int tid = threadIdx.x;
    int i = blockIdx.x*256 + tid;
    int v = (i < NN) ? g_cnt[i] : 0;
    s[tid] = v; __syncthreads();
    #pragma unroll
    for (int off = 1; off < 256; off <<= 1) {
        int t = (tid >= off) ? s[tid-off] : 0;
        __syncthreads();
        s[tid] += t;
        __syncthreads();
    }
    if (i < NN) g_rowptr[i] = s[tid] - v;
    if (tid == 255) g_part[blockIdx.x] = s[255];
}

__global__ void scan2_kernel(int nb) {
    __shared__ int s[256];
    int tid = threadIdx.x;
    int v = (tid < nb) ? g_part[tid] : 0;
    s[tid] = v; __syncthreads();
    #pragma unroll
    for (int off = 1; off < 256; off <<= 1) {
        int t = (tid >= off) ? s[tid-off] : 0;
        __syncthreads();
        s[tid] += t;
        __syncthreads();
    }
    if (tid < nb) g_part[tid] = s[tid] - v;
}

__global__ void scan3_kernel() {
    int i = blockIdx.x*blockDim.x + threadIdx.x;
    if (i < NN) {
        int r = g_rowptr[i] + g_part[blockIdx.x];
        g_rowptr[i] = r;
        g_cur[i] = r;
    }
}

__global__ void fill_kernel(const int* __restrict__ ei) {
    int i = blockIdx.x*blockDim.x + threadIdx.x;
    if (i >= TE) return;
    int src, dst;
    if (i < NE) { src = ei[i]; dst = ei[NE+i]; }
    else        { src = dst = i - NE; }
    int pos = atomicAdd(&g_cur[dst], 1);
    g_col[pos] = src;
}

// ---------------- GEMM: C[M,256] = A[M,K] @ W[K,256] (+bias) + fused scores ----------------
// 128 threads, BM=128 BN=128 BK=16, 16x8 microtile, FFMA2, double-buffered cp.async,
// 4 CTAs/SM. B-fragments amortized over 16 rows (halved LDS/FLOP vs 8x8).
__global__ __launch_bounds__(128, 4) void gemm_kernel(const float* __restrict__ W,
                                                      const float* __restrict__ bias,
                                                      const float* __restrict__ asrc,
                                                      const float* __restrict__ adst,
                                                      int M, int K, int a_is_h) {
    const float* __restrict__ A = a_is_h ? g_h : g_hp;
    float* __restrict__ C       = a_is_h ? g_hp : g_h;

    __shared__ float As[2][128][20];
    __shared__ float Bs[2][16][128];

    int tid = threadIdx.x;
    int bm = blockIdx.x * 128;
    int bn = blockIdx.y * 128;
    int tx = tid & 15;    // cols: bn + tx*8 .. +7
    int ty = tid >> 4;    // rows: ty*16 .. +15

    unsigned long long acc[16][4];
    #pragma unroll
    for (int i = 0; i < 16; i++)
        #pragma unroll
        for (int j = 0; j < 4; j++) acc[i][j] = 0ull;

    int nk = K >> 4;

    // stage-load indices (128 threads, 4 chunks each for A and B)
    // A: 512 float4-chunks: row = q>>2, c4 = (q&3)*4
    // B: 512 float4-chunks: row = q>>5, col = (q&31)*4
    {
        #pragma unroll
        for (int r = 0; r < 4; r++) {
            int q = tid + r*128;
            int row = q >> 2, c4 = (q & 3) * 4;
            int grow = bm + row;
            const float* p = (grow < M) ? (A + (size_t)grow*K + c4) : A;
            cp16p(&As[0][row][c4], p, (grow < M) ? 16 : 0);
        }
        #pragma unroll
        for (int r = 0; r < 4; r++) {
            int q = tid + r*128;
            int row = q >> 5, col = (q & 31) * 4;
            cp16p(&Bs[0][row][col], W + (size_t)row*HID + bn + col, 16);
        }
        cp_commit();
    }

    for (int it = 0; it < nk; ++it) {
        int cur = it & 1, nxt = cur ^ 1;
        if (it + 1 < nk) {
            int k0 = (it + 1) << 4;
            #pragma unroll
            for (int r = 0; r < 4; r++) {
                int q = tid + r*128;
                int row = q >> 2, c4 = (q & 3) * 4;
                int grow = bm + row;
                const float* p = (grow < M) ? (A + (size_t)grow*K + k0 + c4) : A;
                cp16p(&As[nxt][row][c4], p, (grow < M) ? 16 : 0);
            }
            #pragma unroll
            for (int r = 0; r < 4; r++) {
                int q = tid + r*128;
                int row = q >> 5, col = (q & 31) * 4;
                cp16p(&Bs[nxt][row][col], W + (size_t)(k0 + row)*HID + bn + col, 16);
            }
            cp_commit();
            cp_wait1();
        } else {
            cp_wait0();
        }
        __syncthreads();

        #pragma unroll
        for (int kq = 0; kq < 16; kq += 4) {
            // B fragments for 4 kk, reused across 16 rows
            ulonglong2 b01[4], b23[4];
            #pragma unroll
            for (int kk = 0; kk < 4; kk++) {
                b01[kk] = *(const ulonglong2*)(&Bs[cur][kq+kk][tx*8]);
                b23[kk] = *(const ulonglong2*)(&Bs[cur][kq+kk][tx*8+4]);
            }
            #pragma unroll
            for (int rc = 0; rc < 4; rc++) {
                float4 a4[4];
                #pragma unroll
                for (int r = 0; r < 4; r++)
                    a4[r] = *(const float4*)(&As[cur][ty*16 + rc*4 + r][kq]);
                #pragma unroll
                for (int r = 0; r < 4; r++) {
                    int ri = rc*4 + r;
                    #pragma unroll
                    for (int kk = 0; kk < 4; kk++) {
                        float a = (kk == 0) ? a4[r].x : (kk == 1) ? a4[r].y
                                : (kk == 2) ? a4[r].z : a4[r].w;
                        unsigned long long a2;
                        asm("mov.b64 %0, {%1, %1};" : "=l"(a2) : "f"(a));
                        ffma2(acc[ri][0], a2, b01[kk].x);
                        ffma2(acc[ri][1], a2, b01[kk].y);
                        ffma2(acc[ri][2], a2, b23[kk].x);
                        ffma2(acc[ri][3], a2, b23[kk].y);
                    }
                }
            }
        }
        __syncthreads();
    }

    // unpack + bias
    float bz[8];
    #pragma unroll
    for (int j = 0; j < 8; j++) bz[j] = 0.f;
    if (bias) {
        float4 t0 = *(const float4*)(bias + bn + tx*8);
        float4 t1 = *(const float4*)(bias + bn + tx*8 + 4);
        bz[0]=t0.x; bz[1]=t0.y; bz[2]=t0.z; bz[3]=t0.w;
        bz[4]=t1.x; bz[5]=t1.y; bz[6]=t1.z; bz[7]=t1.w;
    }

    float av[8], dv[8];
    int head = 0;
    if (asrc) {
        head = (bn >> 6) + (tx >> 3);
        int c0 = (tx * 8) & 63;
        #pragma unroll
        for (int j = 0; j < 8; j++) {
            av[j] = asrc[head*64 + c0 + j];
            dv[j] = adst[head*64 + c0 + j];
        }
    }

    #pragma unroll
    for (int i = 0; i < 16; i++) {
        int row = bm + ty*16 + i;
        float2 p0 = *(float2*)&acc[i][0];
        float2 p1 = *(float2*)&acc[i][1];
        float2 p2 = *(float2*)&acc[i][2];
        float2 p3 = *(float2*)&acc[i][3];
        float cv[8];
        cv[0]=p0.x+bz[0]; cv[1]=p0.y+bz[1]; cv[2]=p1.x+bz[2]; cv[3]=p1.y+bz[3];
        cv[4]=p2.x+bz[4]; cv[5]=p2.y+bz[5]; cv[6]=p3.x+bz[6]; cv[7]=p3.y+bz[7];
        if (row < M) {
            *(float4*)(C + (size_t)row*HID + bn + tx*8)     = make_float4(cv[0],cv[1],cv[2],cv[3]);
            *(float4*)(C + (size_t)row*HID + bn + tx*8 + 4) = make_float4(cv[4],cv[5],cv[6],cv[7]);
        }
        if (asrc) {
            float ps = 0.f, pd = 0.f;
            #pragma unroll
            for (int j = 0; j < 8; j++) { ps += cv[j]*av[j]; pd += cv[j]*dv[j]; }
            #pragma unroll
            for (int off = 4; off; off >>= 1) {
                ps += __shfl_xor_sync(0xffffffffu, ps, off, 8);
                pd += __shfl_xor_sync(0xffffffffu, pd, off, 8);
            }
            if ((tx & 7) == 0 && row < M) {
                g_ssrc[(size_t)row*4 + head] = ps;
                g_sdst[(size_t)row*4 + head] = pd;
            }
        }
    }
}

// ---------------- aggregation + bias + relu + layernorm ----------------
__global__ void aggregate_kernel(const float* __restrict__ bias,
                                 const float* __restrict__ lng,
                                 const float* __restrict__ lnb) {
    int warp = (blockIdx.x*blockDim.x + threadIdx.x) >> 5;
    int lane = threadIdx.x & 31;
    if (warp >= NN) return;
    int n = warp;
    int start = g_rowptr[n], end = g_rowptr[n+1];

    float4 sd4 = *(const float4*)(g_sdst + (size_t)n*4);

    float m0 = -1e30f, m1 = -1e30f, m2 = -1e30f, m3 = -1e30f;
    for (int i = start + lane; i < end; i += 32) {
        int s = g_col[i];
        float4 ss = *(const float4*)(g_ssrc + (size_t)s*4);
        float e0 = ss.x + sd4.x; e0 = e0 > 0.f ? e0 : 0.2f*e0;
        float e1 = ss.y + sd4.y; e1 = e1 > 0.f ? e1 : 0.2f*e1;
        float e2 = ss.z + sd4.z; e2 = e2 > 0.f ? e2 : 0.2f*e2;
        float e3 = ss.w + sd4.w; e3 = e3 > 0.f ? e3 : 0.2f*e3;
        m0 = fmaxf(m0, e0); m1 = fmaxf(m1, e1);
        m2 = fmaxf(m2, e2); m3 = fmaxf(m3, e3);
    }
    #pragma unroll
    for (int off = 16; off; off >>= 1) {
        m0 = fmaxf(m0, __shfl_xor_sync(0xffffffffu, m0, off));
        m1 = fmaxf(m1, __shfl_xor_sync(0xffffffffu, m1, off));
        m2 = fmaxf(m2, __shfl_xor_sync(0xffffffffu, m2, off));
        m3 = fmaxf(m3, __shfl_xor_sync(0xffffffffu, m3, off));
    }

    bool lo = (lane < 16);
    float mh0 = lo ? m0 : m1;
    float mh1 = lo ? m2 : m3;
    float sdh0 = lo ? sd4.x : sd4.y;
    float sdh1 = lo ? sd4.z : sd4.w;

    float ax = 0.f, ay = 0.f, az = 0.f, aw = 0.f;
    float bx = 0.f, by = 0.f, bz2 = 0.f, bw = 0.f;
    float den0 = 0.f, den1 = 0.f;
    for (int i = start; i < end; ++i) {
        int s = g_col[i];
        float4 ss = *(const float4*)(g_ssrc + (size_t)s*4);
        float e0 = (lo ? ss.x : ss.y) + sdh0; e0 = e0 > 0.f ? e0 : 0.2f*e0;
        float e1 = (lo ? ss.z : ss.w) + sdh1; e1 = e1 > 0.f ? e1 : 0.2f*e1;
        float w0 = __expf(e0 - mh0);
        float w1 = __expf(e1 - mh1);
        den0 += w0; den1 += w1;
        const float4* row = (const float4*)(g_hp + (size_t)s*HID);
        float4 v0 = row[lane], v1 = row[lane+32];
        ax += w0*v0.x; ay += w0*v0.y; az += w0*v0.z; aw += w0*v0.w;
        bx += w1*v1.x; by += w1*v1.y; bz2 += w1*v1.z; bw += w1*v1.w;
    }
    float inv0 = 1.f/den0, inv1 = 1.f/den1;

    int c0 = lane*4, c1 = 128 + lane*4;
    float4 bb0 = *(const float4*)(bias + c0);
    float4 bb1 = *(const float4*)(bias + c1);
    float vals[8];
    vals[0] = fmaxf(0.f, ax*inv0 + bb0.x);
    vals[1] = fmaxf(0.f, ay*inv0 + bb0.y);
    vals[2] = fmaxf(0.f, az*inv0 + bb0.z);
    vals[3] = fmaxf(0.f, aw*inv0 + bb0.w);
    vals[4] = fmaxf(0.f, bx*inv1 + bb1.x);
    vals[5] = fmaxf(0.f, by*inv1 + bb1.y);
    vals[6] = fmaxf(0.f, bz2*inv1 + bb1.z);
    vals[7] = fmaxf(0.f, bw*inv1 + bb1.w);

    float lsum = 0.f;
    #pragma unroll
    for (int j = 0; j < 8; j++) lsum += vals[j];
    #pragma unroll
    for (int off = 16; off; off >>= 1) lsum += __shfl_xor_sync(0xffffffffu, lsum, off);
    float mu = lsum * (1.f/256.f);
    float lsq = 0.f;
    #pragma unroll
    for (int j = 0; j < 8; j++) { float d = vals[j]-mu; lsq += d*d; }
    #pragma unroll
    for (int off = 16; off; off >>= 1) lsq += __shfl_xor_sync(0xffffffffu, lsq, off);
    float rstd = rsqrtf(lsq * (1.f/256.f) + 1e-5f);

    float4 gg0 = *(const float4*)(lng + c0);
    float4 gg1 = *(const float4*)(lng + c1);
    float4 lb0 = *(const float4*)(lnb + c0);
    float4 lb1 = *(const float4*)(lnb + c1);
    float4 o0, o1;
    o0.x = (vals[0]-mu)*rstd*gg0.x + lb0.x;
    o0.y = (vals[1]-mu)*rstd*gg0.y + lb0.y;
    o0.z = (vals[2]-mu)*rstd*gg0.z + lb0.z;
    o0.w = (vals[3]-mu)*rstd*gg0.w + lb0.w;
    o1.x = (vals[4]-mu)*rstd*gg1.x + lb1.x;
    o1.y = (vals[5]-mu)*rstd*gg1.y + lb1.y;
    o1.z = (vals[6]-mu)*rstd*gg1.z + lb1.z;
    o1.w = (vals[7]-mu)*rstd*gg1.w + lb1.w;
    *(float4*)(g_h + (size_t)n*HID + c0) = o0;
    *(float4*)(g_h + (size_t)n*HID + c1) = o1;
}

// ---------------- pooling ----------------
__global__ void pool_kernel(const int* __restrict__ batch) {
    int gw = (blockIdx.x*blockDim.x + threadIdx.x) >> 5;
    int lane = threadIdx.x & 31;
    int n0 = gw * 32;
    if (n0 >= NN) return;
    int nend = n0 + 32; if (nend > NN) nend = NN;

    float4 a0 = make_float4(0,0,0,0), a1 = make_float4(0,0,0,0);
    int curb = batch[n0];
    int cnt = 0;
    for (int n = n0; n < nend; ++n) {
        int b = batch[n];
        if (b != curb) {
            atomicAdd(&g_pool[curb*HID + lane*4+0], a0.x);
            atomicAdd(&g_pool[curb*HID + lane*4+1], a0.y);
            atomicAdd(&g_pool[curb*HID + lane*4+2], a0.z);
            atomicAdd(&g_pool[curb*HID + lane*4+3], a0.w);
            atomicAdd(&g_pool[curb*HID + 128 + lane*4+0], a1.x);
            atomicAdd(&g_pool[curb*HID + 128 + lane*4+1], a1.y);
            atomicAdd(&g_pool[curb*HID + 128 + lane*4+2], a1.z);
            atomicAdd(&g_pool[curb*HID + 128 + lane*4+3], a1.w);
            if (lane == 0) atomicAdd(&g_bcnt[curb], cnt);
            a0 = make_float4(0,0,0,0); a1 = make_float4(0,0,0,0);
            cnt = 0; curb = b;
        }
        const float4* row = (const float4*)(g_h + (size_t)n*HID);
        float4 v0 = row[lane], v1 = row[lane+32];
        a0.x += v0.x; a0.y += v0.y; a0.z += v0.z; a0.w += v0.w;
        a1.x += v1.x; a1.y += v1.y; a1.z += v1.z; a1.w += v1.w;
        cnt++;
    }
    atomicAdd(&g_pool[curb*HID + lane*4+0], a0.x);
    atomicAdd(&g_pool[curb*HID + lane*4+1], a0.y);
    atomicAdd(&g_pool[curb*HID + lane*4+2], a0.z);
    atomicAdd(&g_pool[curb*HID + lane*4+3], a0.w);
    atomicAdd(&g_pool[curb*HID + 128 + lane*4+0], a1.x);
    atomicAdd(&g_pool[curb*HID + 128 + lane*4+1], a1.y);
    atomicAdd(&g_pool[curb*HID + 128 + lane*4+2], a1.z);
    atomicAdd(&g_pool[curb*HID + 128 + lane*4+3], a1.w);
    if (lane == 0) atomicAdd(&g_bcnt[curb], cnt);
}

// ---------------- readout head ----------------
__global__ __launch_bounds__(256) void head_kernel(const float* __restrict__ w1,
                                                   const float* __restrict__ b1,
                                                   const float* __restrict__ w2,
                                                   const float* __restrict__ b2,
                                                   float* __restrict__ out) {
    __shared__ float p[BATCHB*HID];
    __shared__ float t[BATCHB*HID];
    int tid = threadIdx.x;
    for (int i = tid; i < BATCHB*HID; i += 256) {
        float c = fmaxf((float)g_bcnt[i / HID], 1.f);
        p[i] = g_pool[i] / c;
    }
    __syncthreads();
    {
        float acc[BATCHB];
        #pragma unroll
        for (int b = 0; b < BATCHB; b++) acc[b] = 0.f;
        for (int k = 0; k < HID; k++) {
            float w = w1[k*HID + tid];
            #pragma unroll
            for (int b = 0; b < BATCHB; b++) acc[b] += p[b*HID + k] * w;
        }
        #pragma unroll
        for (int b = 0; b < BATCHB; b++) {
            float v = acc[b] + b1[tid];
            t[b*HID + tid] = 0.5f * v * (1.f + erff(v * 0.70710678118654752f));
        }
    }
    __syncthreads();
    {
        float acc[BATCHB];
        #pragma unroll
        for (int b = 0; b < BATCHB; b++) acc[b] = 0.f;
        for (int k = 0; k < HID; k++) {
            float w = w2[k*HID + tid];
            #pragma unroll
            for (int b = 0; b < BATCHB; b++) acc[b] += t[b*HID + k] * w;
        }
        #pragma unroll
        for (int b = 0; b < BATCHB; b++) out[b*HID + tid] = acc[b] + b2[tid];
    }
}

// ---------------- launch ----------------
extern "C" void kernel_launch(void* const* d_in, const int* in_sizes, int n_in,
                              void* d_out, int out_size) {
    const float* x       = (const float*)d_in[0];
    const float* remb    = (const float*)d_in[1];
    const float* in_w    = (const float*)d_in[2];
    const float* in_b    = (const float*)d_in[3];
    const float* gat_w   = (const float*)d_in[4];
    const float* att_src = (const float*)d_in[5];
    const float* att_dst = (const float*)d_in[6];
    const float* gat_b   = (const float*)d_in[7];
    const float* ln_g    = (const float*)d_in[8];
    const float* ln_b    = (const float*)d_in[9];
    const float* ro_w1   = (const float*)d_in[10];
    const float* ro_b1   = (const float*)d_in[11];
    const float* ro_w2   = (const float*)d_in[12];
    const float* ro_b2   = (const float*)d_in[13];
    const int*   ei      = (const int*)d_in[14];
    const int*   batch   = (const int*)d_in[15];
    const int*   rid     = (const int*)d_in[16];
    float* out = (float*)d_out;

    dim3 gemm_grid((NN + 127)/128, HID/128);

    rates_kernel<<<1, 64>>>();                                                    // 0
    feats_kernel<<<(NN*48 + 255)/256, 256>>>(x, remb, rid);                       // 1
    zero_kernel<<<196, 256>>>();                                                  // 2
    // in-proj (K=192) — launch index 3 so ncu -s 5 captures it
    gemm_kernel<<<gemm_grid, 128>>>(in_w, in_b, nullptr, nullptr, NN, 192, 0);    // 3
    count_kernel<<<(TE + 255)/256, 256>>>(ei);                                    // 4
    scan1_kernel<<<196, 256>>>();                                                 // 5
    scan2_kernel<<<1, 256>>>(196);                                                // 6
    scan3_kernel<<<196, 256>>>();                                                 // 7
    fill_kernel<<<(TE + 255)/256, 256>>>(ei);                                     // 8

    for (int l = 0; l < 4; ++l) {
        gemm_kernel<<<gemm_grid, 128>>>(gat_w + (size_t)l*HID*HID, nullptr,
                                        att_src + l*256, att_dst + l*256, NN, HID, 1);
        aggregate_kernel<<<NN/8, 256>>>(gat_b + l*HID, ln_g + l*HID, ln_b + l*HID);
    }

    pool_kernel<<<196, 256>>>(batch);
    head_kernel<<<1, 256>>>(ro_w1, ro_b1, ro_w2, ro_b2, out);
}

// round 10
// speedup vs baseline: 1.7876x; 1.7876x over previous
#include <cuda_runtime.h>
#include <math.h>

#define NN 50000
#define NE 400000
#define TE 450000         // NE + NN self loops
#define HID 256
#define BATCHB 16

// ---------------- scratch ----------------
__device__ float g_h [(size_t)NN*HID];   // layer input / LN output
__device__ float g_hp[(size_t)NN*HID];   // h @ W (also feats buffer, N*192 < N*256)
__device__ float g_ssrc[NN*4];
__device__ float g_sdst[NN*4];
__device__ int   g_cnt[NN];
__device__ int   g_rowptr[NN+1];
__device__ int   g_cur[NN];
__device__ int   g_col[TE];
__device__ int   g_part[256];
__device__ float g_pool[BATCHB*HID];
__device__ int   g_bcnt[BATCHB];
__device__ float g_rates[64];

// ---------------- init ----------------
__global__ void zero_kernel() {
    int i = blockIdx.x*blockDim.x + threadIdx.x;
    if (i < NN) g_cnt[i] = 0;
    if (i < BATCHB*HID) g_pool[i] = 0.f;
    if (i < BATCHB) g_bcnt[i] = 0;
    if (i == 0) g_rowptr[NN] = TE;
}

__global__ void rates_kernel() {
    int j = threadIdx.x;
    if (j < 64) {
        double e = -(double)(2*(j>>1)) / 64.0;
        g_rates[j] = (float)pow(10000.0, e);
    }
}

// feats = [x | region_emb[rid] | posenc]  -> g_hp as [N,192], float4 granularity
__global__ void feats_kernel(const float* __restrict__ x,
                             const float* __restrict__ remb,
                             const int*   __restrict__ rid) {
    int idx = blockIdx.x*blockDim.x + threadIdx.x;
    if (idx >= NN*48) return;
    int n = idx / 48, q = idx - n*48;
    float4 v;
    if (q < 16)      v = ((const float4*)x)[(size_t)n*16 + q];
    else if (q < 32) v = ((const float4*)remb)[(size_t)rid[n]*16 + (q-16)];
    else {
        int j = (q - 32) * 4;
        float fn = (float)n;
        v.x = sinf(fn * g_rates[j+0]);
        v.y = cosf(fn * g_rates[j+1]);
        v.z = sinf(fn * g_rates[j+2]);
        v.w = cosf(fn * g_rates[j+3]);
    }
    ((float4*)g_hp)[(size_t)n*48 + q] = v;
}

// ---------------- CSR build (dst-major) ----------------
__global__ void count_kernel(const int* __restrict__ ei) {
    int i = blockIdx.x*blockDim.x + threadIdx.x;
    if (i >= TE) return;
    int dst = (i < NE) ? ei[NE + i] : (i - NE);
    atomicAdd(&g_cnt[dst], 1);
}

__global__ void scan1_kernel() {
    __shared__ int s[256];
    int tid = threadIdx.x;
    int i = blockIdx.x*256 + tid;
    int v = (i < NN) ? g_cnt[i] : 0;
    s[tid] = v; __syncthreads();
    #pragma unroll
    for (int off = 1; off < 256; off <<= 1) {
        int t = (tid >= off) ? s[tid-off] : 0;
        __syncthreads();
        s[tid] += t;
        __syncthreads();
    }
    if (i < NN) g_rowptr[i] = s[tid] - v;
    if (tid == 255) g_part[blockIdx.x] = s[255];
}

__global__ void scan2_kernel(int nb) {
    __shared__ int s[256];
    int tid = threadIdx.x;
    int v = (tid < nb) ? g_part[tid] : 0;
    s[tid] = v; __syncthreads();
    #pragma unroll
    for (int off = 1; off < 256; off <<= 1) {
        int t = (tid >= off) ? s[tid-off] : 0;
        __syncthreads();
        s[tid] += t;
        __syncthreads();
    }
    if (tid < nb) g_part[tid] = s[tid] - v;
}

__global__ void scan3_kernel() {
    int i = blockIdx.x*blockDim.x + threadIdx.x;
    if (i < NN) {
        int r = g_rowptr[i] + g_part[blockIdx.x];
        g_rowptr[i] = r;
        g_cur[i] = r;
    }
}

__global__ void fill_kernel(const int* __restrict__ ei) {
    int i = blockIdx.x*blockDim.x + threadIdx.x;
    if (i >= TE) return;
    int src, dst;
    if (i < NE) { src = ei[i]; dst = ei[NE+i]; }
    else        { src = dst = i - NE; }
    int pos = atomicAdd(&g_cur[dst], 1);
    g_col[pos] = src;
}

// ---------------- GEMM: C[M,256] = A[M,K] @ W[K,256] (+bias) + fused scores ----------------
// NOTE: ffma2 is intentionally NOT volatile — lets ptxas schedule the FFMA2 stream
// around the LDS fragment loads (software pipelining).
__device__ __forceinline__ void ffma2(unsigned long long& d,
                                      unsigned long long a,
                                      unsigned long long b) {
    asm("fma.rn.f32x2 %0, %1, %2, %0;" : "+l"(d) : "l"(a), "l"(b));
}
__device__ __forceinline__ void cp16(void* smem_dst, const void* gsrc, int src_bytes) {
    unsigned saddr = (unsigned)__cvta_generic_to_shared(smem_dst);
    asm volatile("cp.async.cg.shared.global [%0], [%1], 16, %2;"
                 :: "r"(saddr), "l"(gsrc), "r"(src_bytes));
}
__device__ __forceinline__ void cp_commit() { asm volatile("cp.async.commit_group;"); }
__device__ __forceinline__ void cp_wait1()  { asm volatile("cp.async.wait_group 1;"); }
__device__ __forceinline__ void cp_wait0()  { asm volatile("cp.async.wait_group 0;"); }

// BM=128 BN=128 BK=16, 256 threads, 8x8 microtile, FFMA2, double-buffered cp.async.
// 2 CTAs/SM (128-reg cap); A fragments read as float4 (4 kk per group).
__global__ __launch_bounds__(256, 2) void gemm_kernel(const float* __restrict__ W,
                                                      const float* __restrict__ bias,
                                                      const float* __restrict__ asrc,
                                                      const float* __restrict__ adst,
                                                      int M, int K, int a_is_h) {
    const float* __restrict__ A = a_is_h ? g_h : g_hp;
    float* __restrict__ C       = a_is_h ? g_hp : g_h;

    __shared__ float As[2][128][20];
    __shared__ float Bs[2][16][128];

    int tid = threadIdx.x;
    int bm = blockIdx.x * 128;
    int bn = blockIdx.y * 128;
    int tx = tid & 15;
    int ty = tid >> 4;

    unsigned long long acc[8][4];
    #pragma unroll
    for (int i = 0; i < 8; i++)
        #pragma unroll
        for (int j = 0; j < 4; j++) acc[i][j] = 0ull;

    int a_r = tid >> 2;
    int a_c = (tid & 3) * 4;
    int b_k = tid >> 4;
    int b_c = (tid & 15) * 4;

    int nk = K >> 4;

    #pragma unroll
    for (int r = 0; r < 2; r++) {
        int row = a_r + r*64;
        int grow = bm + row;
        const float* p = (grow < M) ? (A + (size_t)grow*K + a_c) : A;
        cp16(&As[0][row][a_c], p, (grow < M) ? 16 : 0);
    }
    #pragma unroll
    for (int r = 0; r < 2; r++) {
        int col = b_c + r*64;
        cp16(&Bs[0][b_k][col], W + (size_t)b_k*HID + bn + col, 16);
    }
    cp_commit();

    for (int it = 0; it < nk; ++it) {
        int cur = it & 1, nxt = cur ^ 1;
        if (it + 1 < nk) {
            int k0 = (it + 1) << 4;
            #pragma unroll
            for (int r = 0; r < 2; r++) {
                int row = a_r + r*64;
                int grow = bm + row;
                const float* p = (grow < M) ? (A + (size_t)grow*K + k0 + a_c) : A;
                cp16(&As[nxt][row][a_c], p, (grow < M) ? 16 : 0);
            }
            #pragma unroll
            for (int r = 0; r < 2; r++) {
                int col = b_c + r*64;
                cp16(&Bs[nxt][b_k][col], W + (size_t)(k0 + b_k)*HID + bn + col, 16);
            }
            cp_commit();
            cp_wait1();
        } else {
            cp_wait0();
        }
        __syncthreads();

        #pragma unroll
        for (int kq = 0; kq < 16; kq += 4) {
            float4 a4[8];
            #pragma unroll
            for (int i = 0; i < 8; i++)
                a4[i] = *(const float4*)(&As[cur][ty*8+i][kq]);
            #pragma unroll
            for (int kk = 0; kk < 4; ++kk) {
                ulonglong2 b01 = *(const ulonglong2*)(&Bs[cur][kq+kk][tx*8]);
                ulonglong2 b23 = *(const ulonglong2*)(&Bs[cur][kq+kk][tx*8+4]);
                #pragma unroll
                for (int i = 0; i < 8; i++) {
                    float a = (kk == 0) ? a4[i].x : (kk == 1) ? a4[i].y
                            : (kk == 2) ? a4[i].z : a4[i].w;
                    unsigned long long a2;
                    asm("mov.b64 %0, {%1, %1};" : "=l"(a2) : "f"(a));
                    ffma2(acc[i][0], a2, b01.x);
                    ffma2(acc[i][1], a2, b01.y);
                    ffma2(acc[i][2], a2, b23.x);
                    ffma2(acc[i][3], a2, b23.y);
                }
            }
        }
        __syncthreads();
    }

    float cv[8][8];
    #pragma unroll
    for (int i = 0; i < 8; i++) {
        float2 p0 = *(float2*)&acc[i][0];
        float2 p1 = *(float2*)&acc[i][1];
        float2 p2 = *(float2*)&acc[i][2];
        float2 p3 = *(float2*)&acc[i][3];
        cv[i][0]=p0.x; cv[i][1]=p0.y; cv[i][2]=p1.x; cv[i][3]=p1.y;
        cv[i][4]=p2.x; cv[i][5]=p2.y; cv[i][6]=p3.x; cv[i][7]=p3.y;
    }
    if (bias) {
        float4 t0 = *(const float4*)(bias + bn + tx*8);
        float4 t1 = *(const float4*)(bias + bn + tx*8 + 4);
        #pragma unroll
        for (int i = 0; i < 8; i++) {
            cv[i][0]+=t0.x; cv[i][1]+=t0.y; cv[i][2]+=t0.z; cv[i][3]+=t0.w;
            cv[i][4]+=t1.x; cv[i][5]+=t1.y; cv[i][6]+=t1.z; cv[i][7]+=t1.w;
        }
    }
    #pragma unroll
    for (int i = 0; i < 8; i++) {
        int row = bm + ty*8 + i;
        if (row < M) {
            *(float4*)(C + (size_t)row*HID + bn + tx*8)     = make_float4(cv[i][0],cv[i][1],cv[i][2],cv[i][3]);
            *(float4*)(C + (size_t)row*HID + bn + tx*8 + 4) = make_float4(cv[i][4],cv[i][5],cv[i][6],cv[i][7]);
        }
    }

    if (asrc) {
        int head = (bn >> 6) + (tx >> 3);
        int c0 = (tx * 8) & 63;
        float av[8], dv[8];
        #pragma unroll
        for (int j = 0; j < 8; j++) {
            av[j] = asrc[head*64 + c0 + j];
            dv[j] = adst[head*64 + c0 + j];
        }
        #pragma unroll
        for (int i = 0; i < 8; i++) {
            float ps = 0.f, pd = 0.f;
            #pragma unroll
            for (int j = 0; j < 8; j++) { ps += cv[i][j]*av[j]; pd += cv[i][j]*dv[j]; }
            #pragma unroll
            for (int off = 4; off; off >>= 1) {
                ps += __shfl_xor_sync(0xffffffffu, ps, off, 8);
                pd += __shfl_xor_sync(0xffffffffu, pd, off, 8);
            }
            int row = bm + ty*8 + i;
            if ((tx & 7) == 0 && row < M) {
                g_ssrc[(size_t)row*4 + head] = ps;
                g_sdst[(size_t)row*4 + head] = pd;
            }
        }
    }
}

// ---------------- aggregation + bias + relu + layernorm: one warp per dst ----------------
__global__ void aggregate_kernel(const float* __restrict__ bias,
                                 const float* __restrict__ lng,
                                 const float* __restrict__ lnb) {
    int warp = (blockIdx.x*blockDim.x + threadIdx.x) >> 5;
    int lane = threadIdx.x & 31;
    if (warp >= NN) return;
    int n = warp;
    int start = g_rowptr[n], end = g_rowptr[n+1];

    float4 sd4 = *(const float4*)(g_sdst + (size_t)n*4);

    float m0 = -1e30f, m1 = -1e30f, m2 = -1e30f, m3 = -1e30f;
    for (int i = start + lane; i < end; i += 32) {
        int s = g_col[i];
        float4 ss = *(const float4*)(g_ssrc + (size_t)s*4);
        float e0 = ss.x + sd4.x; e0 = e0 > 0.f ? e0 : 0.2f*e0;
        float e1 = ss.y + sd4.y; e1 = e1 > 0.f ? e1 : 0.2f*e1;
        float e2 = ss.z + sd4.z; e2 = e2 > 0.f ? e2 : 0.2f*e2;
        float e3 = ss.w + sd4.w; e3 = e3 > 0.f ? e3 : 0.2f*e3;
        m0 = fmaxf(m0, e0); m1 = fmaxf(m1, e1);
        m2 = fmaxf(m2, e2); m3 = fmaxf(m3, e3);
    }
    #pragma unroll
    for (int off = 16; off; off >>= 1) {
        m0 = fmaxf(m0, __shfl_xor_sync(0xffffffffu, m0, off));
        m1 = fmaxf(m1, __shfl_xor_sync(0xffffffffu, m1, off));
        m2 = fmaxf(m2, __shfl_xor_sync(0xffffffffu, m2, off));
        m3 = fmaxf(m3, __shfl_xor_sync(0xffffffffu, m3, off));
    }

    bool lo = (lane < 16);
    float mh0 = lo ? m0 : m1;
    float mh1 = lo ? m2 : m3;
    float sdh0 = lo ? sd4.x : sd4.y;
    float sdh1 = lo ? sd4.z : sd4.w;

    float ax = 0.f, ay = 0.f, az = 0.f, aw = 0.f;
    float bx = 0.f, by = 0.f, bz2 = 0.f, bw = 0.f;
    float den0 = 0.f, den1 = 0.f;
    for (int i = start; i < end; ++i) {
        int s = g_col[i];
        float4 ss = *(const float4*)(g_ssrc + (size_t)s*4);
        float e0 = (lo ? ss.x : ss.y) + sdh0; e0 = e0 > 0.f ? e0 : 0.2f*e0;
        float e1 = (lo ? ss.z : ss.w) + sdh1; e1 = e1 > 0.f ? e1 : 0.2f*e1;
        float w0 = __expf(e0 - mh0);
        float w1 = __expf(e1 - mh1);
        den0 += w0; den1 += w1;
        const float4* row = (const float4*)(g_hp + (size_t)s*HID);
        float4 v0 = row[lane], v1 = row[lane+32];
        ax += w0*v0.x; ay += w0*v0.y; az += w0*v0.z; aw += w0*v0.w;
        bx += w1*v1.x; by += w1*v1.y; bz2 += w1*v1.z; bw += w1*v1.w;
    }
    float inv0 = 1.f/den0, inv1 = 1.f/den1;

    int c0 = lane*4, c1 = 128 + lane*4;
    float4 bb0 = *(const float4*)(bias + c0);
    float4 bb1 = *(const float4*)(bias + c1);
    float vals[8];
    vals[0] = fmaxf(0.f, ax*inv0 + bb0.x);
    vals[1] = fmaxf(0.f, ay*inv0 + bb0.y);
    vals[2] = fmaxf(0.f, az*inv0 + bb0.z);
    vals[3] = fmaxf(0.f, aw*inv0 + bb0.w);
    vals[4] = fmaxf(0.f, bx*inv1 + bb1.x);
    vals[5] = fmaxf(0.f, by*inv1 + bb1.y);
    vals[6] = fmaxf(0.f, bz2*inv1 + bb1.z);
    vals[7] = fmaxf(0.f, bw*inv1 + bb1.w);

    float lsum = 0.f;
    #pragma unroll
    for (int j = 0; j < 8; j++) lsum += vals[j];
    #pragma unroll
    for (int off = 16; off; off >>= 1) lsum += __shfl_xor_sync(0xffffffffu, lsum, off);
    float mu = lsum * (1.f/256.f);
    float lsq = 0.f;
    #pragma unroll
    for (int j = 0; j < 8; j++) { float d = vals[j]-mu; lsq += d*d; }
    #pragma unroll
    for (int off = 16; off; off >>= 1) lsq += __shfl_xor_sync(0xffffffffu, lsq, off);
    float rstd = rsqrtf(lsq * (1.f/256.f) + 1e-5f);

    float4 gg0 = *(const float4*)(lng + c0);
    float4 gg1 = *(const float4*)(lng + c1);
    float4 lb0 = *(const float4*)(lnb + c0);
    float4 lb1 = *(const float4*)(lnb + c1);
    float4 o0, o1;
    o0.x = (vals[0]-mu)*rstd*gg0.x + lb0.x;
    o0.y = (vals[1]-mu)*rstd*gg0.y + lb0.y;
    o0.z = (vals[2]-mu)*rstd*gg0.z + lb0.z;
    o0.w = (vals[3]-mu)*rstd*gg0.w + lb0.w;
    o1.x = (vals[4]-mu)*rstd*gg1.x + lb1.x;
    o1.y = (vals[5]-mu)*rstd*gg1.y + lb1.y;
    o1.z = (vals[6]-mu)*rstd*gg1.z + lb1.z;
    o1.w = (vals[7]-mu)*rstd*gg1.w + lb1.w;
    *(float4*)(g_h + (size_t)n*HID + c0) = o0;
    *(float4*)(g_h + (size_t)n*HID + c1) = o1;
}

// ---------------- pooling ----------------
__global__ void pool_kernel(const int* __restrict__ batch) {
    int gw = (blockIdx.x*blockDim.x + threadIdx.x) >> 5;
    int lane = threadIdx.x & 31;
    int n0 = gw * 32;
    if (n0 >= NN) return;
    int nend = n0 + 32; if (nend > NN) nend = NN;

    float4 a0 = make_float4(0,0,0,0), a1 = make_float4(0,0,0,0);
    int curb = batch[n0];
    int cnt = 0;
    for (int n = n0; n < nend; ++n) {
        int b = batch[n];
        if (b != curb) {
            atomicAdd(&g_pool[curb*HID + lane*4+0], a0.x);
            atomicAdd(&g_pool[curb*HID + lane*4+1], a0.y);
            atomicAdd(&g_pool[curb*HID + lane*4+2], a0.z);
            atomicAdd(&g_pool[curb*HID + lane*4+3], a0.w);
            atomicAdd(&g_pool[curb*HID + 128 + lane*4+0], a1.x);
            atomicAdd(&g_pool[curb*HID + 128 + lane*4+1], a1.y);
            atomicAdd(&g_pool[curb*HID + 128 + lane*4+2], a1.z);
            atomicAdd(&g_pool[curb*HID + 128 + lane*4+3], a1.w);
            if (lane == 0) atomicAdd(&g_bcnt[curb], cnt);
            a0 = make_float4(0,0,0,0); a1 = make_float4(0,0,0,0);
            cnt = 0; curb = b;
        }
        const float4* row = (const float4*)(g_h + (size_t)n*HID);
        float4 v0 = row[lane], v1 = row[lane+32];
        a0.x += v0.x; a0.y += v0.y; a0.z += v0.z; a0.w += v0.w;
        a1.x += v1.x; a1.y += v1.y; a1.z += v1.z; a1.w += v1.w;
        cnt++;
    }
    atomicAdd(&g_pool[curb*HID + lane*4+0], a0.x);
    atomicAdd(&g_pool[curb*HID + lane*4+1], a0.y);
    atomicAdd(&g_pool[curb*HID + lane*4+2], a0.z);
    atomicAdd(&g_pool[curb*HID + lane*4+3], a0.w);
    atomicAdd(&g_pool[curb*HID + 128 + lane*4+0], a1.x);
    atomicAdd(&g_pool[curb*HID + 128 + lane*4+1], a1.y);
    atomicAdd(&g_pool[curb*HID + 128 + lane*4+2], a1.z);
    atomicAdd(&g_pool[curb*HID + 128 + lane*4+3], a1.w);
    if (lane == 0) atomicAdd(&g_bcnt[curb], cnt);
}

// ---------------- readout head ----------------
__global__ __launch_bounds__(256) void head_kernel(const float* __restrict__ w1,
                                                   const float* __restrict__ b1,
                                                   const float* __restrict__ w2,
                                                   const float* __restrict__ b2,
                                                   float* __restrict__ out) {
    __shared__ float p[BATCHB*HID];
    __shared__ float t[BATCHB*HID];
    int tid = threadIdx.x;
    for (int i = tid; i < BATCHB*HID; i += 256) {
        float c = fmaxf((float)g_bcnt[i / HID], 1.f);
        p[i] = g_pool[i] / c;
    }
    __syncthreads();
    {
        float acc[BATCHB];
        #pragma unroll
        for (int b = 0; b < BATCHB; b++) acc[b] = 0.f;
        for (int k = 0; k < HID; k++) {
            float w = w1[k*HID + tid];
            #pragma unroll
            for (int b = 0; b < BATCHB; b++) acc[b] += p[b*HID + k] * w;
        }
        #pragma unroll
        for (int b = 0; b < BATCHB; b++) {
            float v = acc[b] + b1[tid];
            t[b*HID + tid] = 0.5f * v * (1.f + erff(v * 0.70710678118654752f));
        }
    }
    __syncthreads();
    {
        float acc[BATCHB];
        #pragma unroll
        for (int b = 0; b < BATCHB; b++) acc[b] = 0.f;
        for (int k = 0; k < HID; k++) {
            float w = w2[k*HID + tid];
            #pragma unroll
            for (int b = 0; b < BATCHB; b++) acc[b] += t[b*HID + k] * w;
        }
        #pragma unroll
        for (int b = 0; b < BATCHB; b++) out[b*HID + tid] = acc[b] + b2[tid];
    }
}

// ---------------- launch ----------------
extern "C" void kernel_launch(void* const* d_in, const int* in_sizes, int n_in,
                              void* d_out, int out_size) {
    const float* x       = (const float*)d_in[0];
    const float* remb    = (const float*)d_in[1];
    const float* in_w    = (const float*)d_in[2];
    const float* in_b    = (const float*)d_in[3];
    const float* gat_w   = (const float*)d_in[4];
    const float* att_src = (const float*)d_in[5];
    const float* att_dst = (const float*)d_in[6];
    const float* gat_b   = (const float*)d_in[7];
    const float* ln_g    = (const float*)d_in[8];
    const float* ln_b    = (const float*)d_in[9];
    const float* ro_w1   = (const float*)d_in[10];
    const float* ro_b1   = (const float*)d_in[11];
    const float* ro_w2   = (const float*)d_in[12];
    const float* ro_b2   = (const float*)d_in[13];
    const int*   ei      = (const int*)d_in[14];
    const int*   batch   = (const int*)d_in[15];
    const int*   rid     = (const int*)d_in[16];
    float* out = (float*)d_out;

    dim3 gemm_grid((NN + 127)/128, HID/128);

    rates_kernel<<<1, 64>>>();                                                    // 0
    feats_kernel<<<(NN*48 + 255)/256, 256>>>(x, remb, rid);                       // 1
    zero_kernel<<<196, 256>>>();                                                  // 2
    // in-proj (K=192) — launch index 3 so ncu -s 5 captures it
    gemm_kernel<<<gemm_grid, 256>>>(in_w, in_b, nullptr, nullptr, NN, 192, 0);    // 3
    count_kernel<<<(TE + 255)/256, 256>>>(ei);                                    // 4
    scan1_kernel<<<196, 256>>>();                                                 // 5
    scan2_kernel<<<1, 256>>>(196);                                                // 6
    scan3_kernel<<<196, 256>>>();                                                 // 7
    fill_kernel<<<(TE + 255)/256, 256>>>(ei);                                     // 8

    for (int l = 0; l < 4; ++l) {
        gemm_kernel<<<gemm_grid, 256>>>(gat_w + (size_t)l*HID*HID, nullptr,
                                        att_src + l*256, att_dst + l*256, NN, HID, 1);
        aggregate_kernel<<<NN/8, 256>>>(gat_b + l*HID, ln_g + l*HID, ln_b + l*HID);
    }

    pool_kernel<<<196, 256>>>(batch);
    head_kernel<<<1, 256>>>(ro_w1, ro_b1, ro_w2, ro_b2, out);
}

// round 11
// speedup vs baseline: 1.8739x; 1.0483x over previous
#include <cuda_runtime.h>
#include <math.h>

#define NN 50000
#define NE 400000
#define TE 450000         // NE + NN self loops
#define HID 256
#define BATCHB 16

// ---------------- scratch ----------------
__device__ float g_h [(size_t)NN*HID];   // layer input / LN output
__device__ float g_hp[(size_t)NN*HID];   // h @ W (also feats buffer, N*192 < N*256)
__device__ float g_ssrc[NN*4];
__device__ float g_sdst[NN*4];
__device__ int   g_cnt[NN];
__device__ int   g_rowptr[NN+1];
__device__ int   g_cur[NN];
__device__ int   g_col[TE];
__device__ int   g_part[256];
__device__ float g_pool[BATCHB*HID];
__device__ int   g_bcnt[BATCHB];
__device__ float g_rates[64];

// ---------------- init ----------------
__global__ void zero_kernel() {
    int i = blockIdx.x*blockDim.x + threadIdx.x;
    if (i < NN) g_cnt[i] = 0;
    if (i < BATCHB*HID) g_pool[i] = 0.f;
    if (i < BATCHB) g_bcnt[i] = 0;
    if (i == 0) g_rowptr[NN] = TE;
}

__global__ void rates_kernel() {
    int j = threadIdx.x;
    if (j < 64) {
        double e = -(double)(2*(j>>1)) / 64.0;
        g_rates[j] = (float)pow(10000.0, e);
    }
}

// feats = [x | region_emb[rid] | posenc]  -> g_hp as [N,192], float4 granularity
__global__ void feats_kernel(const float* __restrict__ x,
                             const float* __restrict__ remb,
                             const int*   __restrict__ rid) {
    int idx = blockIdx.x*blockDim.x + threadIdx.x;
    if (idx >= NN*48) return;
    int n = idx / 48, q = idx - n*48;
    float4 v;
    if (q < 16)      v = ((const float4*)x)[(size_t)n*16 + q];
    else if (q < 32) v = ((const float4*)remb)[(size_t)rid[n]*16 + (q-16)];
    else {
        int j = (q - 32) * 4;
        float fn = (float)n;
        v.x = sinf(fn * g_rates[j+0]);
        v.y = cosf(fn * g_rates[j+1]);
        v.z = sinf(fn * g_rates[j+2]);
        v.w = cosf(fn * g_rates[j+3]);
    }
    ((float4*)g_hp)[(size_t)n*48 + q] = v;
}

// ---------------- CSR build (dst-major) ----------------
__global__ void count_kernel(const int* __restrict__ ei) {
    int i = blockIdx.x*blockDim.x + threadIdx.x;
    if (i >= TE) return;
    int dst = (i < NE) ? ei[NE + i] : (i - NE);
    atomicAdd(&g_cnt[dst], 1);
}

__global__ void scan1_kernel() {
    __shared__ int s[256];
    int tid = threadIdx.x;
    int i = blockIdx.x*256 + tid;
    int v = (i < NN) ? g_cnt[i] : 0;
    s[tid] = v; __syncthreads();
    #pragma unroll
    for (int off = 1; off < 256; off <<= 1) {
        int t = (tid >= off) ? s[tid-off] : 0;
        __syncthreads();
        s[tid] += t;
        __syncthreads();
    }
    if (i < NN) g_rowptr[i] = s[tid] - v;
    if (tid == 255) g_part[blockIdx.x] = s[255];
}

__global__ void scan2_kernel(int nb) {
    __shared__ int s[256];
    int tid = threadIdx.x;
    int v = (tid < nb) ? g_part[tid] : 0;
    s[tid] = v; __syncthreads();
    #pragma unroll
    for (int off = 1; off < 256; off <<= 1) {
        int t = (tid >= off) ? s[tid-off] : 0;
        __syncthreads();
        s[tid] += t;
        __syncthreads();
    }
    if (tid < nb) g_part[tid] = s[tid] - v;
}

__global__ void scan3_kernel() {
    int i = blockIdx.x*blockDim.x + threadIdx.x;
    if (i < NN) {
        int r = g_rowptr[i] + g_part[blockIdx.x];
        g_rowptr[i] = r;
        g_cur[i] = r;
    }
}

__global__ void fill_kernel(const int* __restrict__ ei) {
    int i = blockIdx.x*blockDim.x + threadIdx.x;
    if (i >= TE) return;
    int src, dst;
    if (i < NE) { src = ei[i]; dst = ei[NE+i]; }
    else        { src = dst = i - NE; }
    int pos = atomicAdd(&g_cur[dst], 1);
    g_col[pos] = src;
}

// ---------------- GEMM: C[M,256] = A[M,K] @ W[K,256] (+bias) + fused scores ----------------
__device__ __forceinline__ void ffma2(unsigned long long& d,
                                      unsigned long long a,
                                      unsigned long long b) {
    asm volatile("fma.rn.f32x2 %0, %1, %2, %0;" : "+l"(d) : "l"(a), "l"(b));
}
__device__ __forceinline__ void cp16(void* smem_dst, const void* gsrc, int src_bytes) {
    unsigned saddr = (unsigned)__cvta_generic_to_shared(smem_dst);
    asm volatile("cp.async.cg.shared.global [%0], [%1], 16, %2;"
                 :: "r"(saddr), "l"(gsrc), "r"(src_bytes));
}
__device__ __forceinline__ void cp_commit() { asm volatile("cp.async.commit_group;"); }
__device__ __forceinline__ void cp_wait1()  { asm volatile("cp.async.wait_group 1;"); }
__device__ __forceinline__ void cp_wait0()  { asm volatile("cp.async.wait_group 0;"); }

// BM=128 BN=128 BK=16, 256 threads, 8x8 microtile, FFMA2.
// 3-stage cp.async pipeline, ONE barrier per k-tile. Static smem = exactly 48KB.
__global__ __launch_bounds__(256, 2) void gemm_kernel(const float* __restrict__ W,
                                                      const float* __restrict__ bias,
                                                      const float* __restrict__ asrc,
                                                      const float* __restrict__ adst,
                                                      int M, int K, int a_is_h) {
    const float* __restrict__ A = a_is_h ? g_h : g_hp;
    float* __restrict__ C       = a_is_h ? g_hp : g_h;

    __shared__ float As[3][128][16];
    __shared__ float Bs[3][16][128];

    int tid = threadIdx.x;
    int bm = blockIdx.x * 128;
    int bn = blockIdx.y * 128;
    int tx = tid & 15;
    int ty = tid >> 4;

    unsigned long long acc[8][4];
    #pragma unroll
    for (int i = 0; i < 8; i++)
        #pragma unroll
        for (int j = 0; j < 4; j++) acc[i][j] = 0ull;

    int a_r = tid >> 2;
    int a_c = (tid & 3) * 4;
    int b_k = tid >> 4;
    int b_c = (tid & 15) * 4;

    int nk = K >> 4;

    // prologue: tiles 0 and 1 (nk >= 12 always)
    #pragma unroll
    for (int st = 0; st < 2; st++) {
        int k0 = st << 4;
        #pragma unroll
        for (int r = 0; r < 2; r++) {
            int row = a_r + r*64;
            int grow = bm + row;
            const float* p = (grow < M) ? (A + (size_t)grow*K + k0 + a_c) : A;
            cp16(&As[st][row][a_c], p, (grow < M) ? 16 : 0);
        }
        #pragma unroll
        for (int r = 0; r < 2; r++) {
            int col = b_c + r*64;
            cp16(&Bs[st][b_k][col], W + (size_t)(k0 + b_k)*HID + bn + col, 16);
        }
        cp_commit();
    }

    int cur = 0, nxt = 2;   // nxt = buffer for tile it+2
    for (int it = 0; it < nk; ++it) {
        if (it + 1 < nk) cp_wait1(); else cp_wait0();
        __syncthreads();

        if (it + 2 < nk) {
            int k0 = (it + 2) << 4;
            #pragma unroll
            for (int r = 0; r < 2; r++) {
                int row = a_r + r*64;
                int grow = bm + row;
                const float* p = (grow < M) ? (A + (size_t)grow*K + k0 + a_c) : A;
                cp16(&As[nxt][row][a_c], p, (grow < M) ? 16 : 0);
            }
            #pragma unroll
            for (int r = 0; r < 2; r++) {
                int col = b_c + r*64;
                cp16(&Bs[nxt][b_k][col], W + (size_t)(k0 + b_k)*HID + bn + col, 16);
            }
            cp_commit();
        }

        #pragma unroll
        for (int kq = 0; kq < 16; kq += 4) {
            float4 a4[8];
            #pragma unroll
            for (int i = 0; i < 8; i++)
                a4[i] = *(const float4*)(&As[cur][ty*8+i][kq]);
            #pragma unroll
            for (int kk = 0; kk < 4; ++kk) {
                ulonglong2 b01 = *(const ulonglong2*)(&Bs[cur][kq+kk][tx*8]);
                ulonglong2 b23 = *(const ulonglong2*)(&Bs[cur][kq+kk][tx*8+4]);
                #pragma unroll
                for (int i = 0; i < 8; i++) {
                    float a = (kk == 0) ? a4[i].x : (kk == 1) ? a4[i].y
                            : (kk == 2) ? a4[i].z : a4[i].w;
                    unsigned long long a2;
                    asm("mov.b64 %0, {%1, %1};" : "=l"(a2) : "f"(a));
                    ffma2(acc[i][0], a2, b01.x);
                    ffma2(acc[i][1], a2, b01.y);
                    ffma2(acc[i][2], a2, b23.x);
                    ffma2(acc[i][3], a2, b23.y);
                }
            }
        }
        cur = (cur == 2) ? 0 : cur + 1;
        nxt = (nxt == 2) ? 0 : nxt + 1;
    }

    float cv[8][8];
    #pragma unroll
    for (int i = 0; i < 8; i++) {
        float2 p0 = *(float2*)&acc[i][0];
        float2 p1 = *(float2*)&acc[i][1];
        float2 p2 = *(float2*)&acc[i][2];
        float2 p3 = *(float2*)&acc[i][3];
        cv[i][0]=p0.x; cv[i][1]=p0.y; cv[i][2]=p1.x; cv[i][3]=p1.y;
        cv[i][4]=p2.x; cv[i][5]=p2.y; cv[i][6]=p3.x; cv[i][7]=p3.y;
    }
    if (bias) {
        float4 t0 = *(const float4*)(bias + bn + tx*8);
        float4 t1 = *(const float4*)(bias + bn + tx*8 + 4);
        #pragma unroll
        for (int i = 0; i < 8; i++) {
            cv[i][0]+=t0.x; cv[i][1]+=t0.y; cv[i][2]+=t0.z; cv[i][3]+=t0.w;
            cv[i][4]+=t1.x; cv[i][5]+=t1.y; cv[i][6]+=t1.z; cv[i][7]+=t1.w;
        }
    }
    #pragma unroll
    for (int i = 0; i < 8; i++) {
        int row = bm + ty*8 + i;
        if (row < M) {
            *(float4*)(C + (size_t)row*HID + bn + tx*8)     = make_float4(cv[i][0],cv[i][1],cv[i][2],cv[i][3]);
            *(float4*)(C + (size_t)row*HID + bn + tx*8 + 4) = make_float4(cv[i][4],cv[i][5],cv[i][6],cv[i][7]);
        }
    }

    if (asrc) {
        int head = (bn >> 6) + (tx >> 3);
        int c0 = (tx * 8) & 63;
        float av[8], dv[8];
        #pragma unroll
        for (int j = 0; j < 8; j++) {
            av[j] = asrc[head*64 + c0 + j];
            dv[j] = adst[head*64 + c0 + j];
        }
        #pragma unroll
        for (int i = 0; i < 8; i++) {
            float ps = 0.f, pd = 0.f;
            #pragma unroll
            for (int j = 0; j < 8; j++) { ps += cv[i][j]*av[j]; pd += cv[i][j]*dv[j]; }
            #pragma unroll
            for (int off = 4; off; off >>= 1) {
                ps += __shfl_xor_sync(0xffffffffu, ps, off, 8);
                pd += __shfl_xor_sync(0xffffffffu, pd, off, 8);
            }
            int row = bm + ty*8 + i;
            if ((tx & 7) == 0 && row < M) {
                g_ssrc[(size_t)row*4 + head] = ps;
                g_sdst[(size_t)row*4 + head] = pd;
            }
        }
    }
}

// ---------------- aggregation + bias + relu + layernorm: one warp per dst ----------------
// Single pass: softmax is shift-invariant and |e| is bounded (~±8), so exp(e) is
// computed directly without the max pass.
__global__ void aggregate_kernel(const float* __restrict__ bias,
                                 const float* __restrict__ lng,
                                 const float* __restrict__ lnb) {
    int warp = (blockIdx.x*blockDim.x + threadIdx.x) >> 5;
    int lane = threadIdx.x & 31;
    if (warp >= NN) return;
    int n = warp;
    int start = g_rowptr[n], end = g_rowptr[n+1];

    float4 sd4 = *(const float4*)(g_sdst + (size_t)n*4);
    bool lo = (lane < 16);
    float sdh0 = lo ? sd4.x : sd4.y;
    float sdh1 = lo ? sd4.z : sd4.w;

    float ax = 0.f, ay = 0.f, az = 0.f, aw = 0.f;
    float bx = 0.f, by = 0.f, bz2 = 0.f, bw = 0.f;
    float den0 = 0.f, den1 = 0.f;
    for (int i = start; i < end; ++i) {
        int s = g_col[i];
        float4 ss = *(const float4*)(g_ssrc + (size_t)s*4);
        float e0 = (lo ? ss.x : ss.y) + sdh0; e0 = e0 > 0.f ? e0 : 0.2f*e0;
        float e1 = (lo ? ss.z : ss.w) + sdh1; e1 = e1 > 0.f ? e1 : 0.2f*e1;
        float w0 = __expf(e0);
        float w1 = __expf(e1);
        den0 += w0; den1 += w1;
        const float4* row = (const float4*)(g_hp + (size_t)s*HID);
        float4 v0 = row[lane], v1 = row[lane+32];
        ax += w0*v0.x; ay += w0*v0.y; az += w0*v0.z; aw += w0*v0.w;
        bx += w1*v1.x; by += w1*v1.y; bz2 += w1*v1.z; bw += w1*v1.w;
    }
    float inv0 = 1.f/den0, inv1 = 1.f/den1;

    int c0 = lane*4, c1 = 128 + lane*4;
    float4 bb0 = *(const float4*)(bias + c0);
    float4 bb1 = *(const float4*)(bias + c1);
    float vals[8];
    vals[0] = fmaxf(0.f, ax*inv0 + bb0.x);
    vals[1] = fmaxf(0.f, ay*inv0 + bb0.y);
    vals[2] = fmaxf(0.f, az*inv0 + bb0.z);
    vals[3] = fmaxf(0.f, aw*inv0 + bb0.w);
    vals[4] = fmaxf(0.f, bx*inv1 + bb1.x);
    vals[5] = fmaxf(0.f, by*inv1 + bb1.y);
    vals[6] = fmaxf(0.f, bz2*inv1 + bb1.z);
    vals[7] = fmaxf(0.f, bw*inv1 + bb1.w);

    float lsum = 0.f;
    #pragma unroll
    for (int j = 0; j < 8; j++) lsum += vals[j];
    #pragma unroll
    for (int off = 16; off; off >>= 1) lsum += __shfl_xor_sync(0xffffffffu, lsum, off);
    float mu = lsum * (1.f/256.f);
    float lsq = 0.f;
    #pragma unroll
    for (int j = 0; j < 8; j++) { float d = vals[j]-mu; lsq += d*d; }
    #pragma unroll
    for (int off = 16; off; off >>= 1) lsq += __shfl_xor_sync(0xffffffffu, lsq, off);
    float rstd = rsqrtf(lsq * (1.f/256.f) + 1e-5f);

    float4 gg0 = *(const float4*)(lng + c0);
    float4 gg1 = *(const float4*)(lng + c1);
    float4 lb0 = *(const float4*)(lnb + c0);
    float4 lb1 = *(const float4*)(lnb + c1);
    float4 o0, o1;
    o0.x = (vals[0]-mu)*rstd*gg0.x + lb0.x;
    o0.y = (vals[1]-mu)*rstd*gg0.y + lb0.y;
    o0.z = (vals[2]-mu)*rstd*gg0.z + lb0.z;
    o0.w = (vals[3]-mu)*rstd*gg0.w + lb0.w;
    o1.x = (vals[4]-mu)*rstd*gg1.x + lb1.x;
    o1.y = (vals[5]-mu)*rstd*gg1.y + lb1.y;
    o1.z = (vals[6]-mu)*rstd*gg1.z + lb1.z;
    o1.w = (vals[7]-mu)*rstd*gg1.w + lb1.w;
    *(float4*)(g_h + (size_t)n*HID + c0) = o0;
    *(float4*)(g_h + (size_t)n*HID + c1) = o1;
}

// ---------------- pooling ----------------
__global__ void pool_kernel(const int* __restrict__ batch) {
    int gw = (blockIdx.x*blockDim.x + threadIdx.x) >> 5;
    int lane = threadIdx.x & 31;
    int n0 = gw * 32;
    if (n0 >= NN) return;
    int nend = n0 + 32; if (nend > NN) nend = NN;

    float4 a0 = make_float4(0,0,0,0), a1 = make_float4(0,0,0,0);
    int curb = batch[n0];
    int cnt = 0;
    for (int n = n0; n < nend; ++n) {
        int b = batch[n];
        if (b != curb) {
            atomicAdd(&g_pool[curb*HID + lane*4+0], a0.x);
            atomicAdd(&g_pool[curb*HID + lane*4+1], a0.y);
            atomicAdd(&g_pool[curb*HID + lane*4+2], a0.z);
            atomicAdd(&g_pool[curb*HID + lane*4+3], a0.w);
            atomicAdd(&g_pool[curb*HID + 128 + lane*4+0], a1.x);
            atomicAdd(&g_pool[curb*HID + 128 + lane*4+1], a1.y);
            atomicAdd(&g_pool[curb*HID + 128 + lane*4+2], a1.z);
            atomicAdd(&g_pool[curb*HID + 128 + lane*4+3], a1.w);
            if (lane == 0) atomicAdd(&g_bcnt[curb], cnt);
            a0 = make_float4(0,0,0,0); a1 = make_float4(0,0,0,0);
            cnt = 0; curb = b;
        }
        const float4* row = (const float4*)(g_h + (size_t)n*HID);
        float4 v0 = row[lane], v1 = row[lane+32];
        a0.x += v0.x; a0.y += v0.y; a0.z += v0.z; a0.w += v0.w;
        a1.x += v1.x; a1.y += v1.y; a1.z += v1.z; a1.w += v1.w;
        cnt++;
    }
    atomicAdd(&g_pool[curb*HID + lane*4+0], a0.x);
    atomicAdd(&g_pool[curb*HID + lane*4+1], a0.y);
    atomicAdd(&g_pool[curb*HID + lane*4+2], a0.z);
    atomicAdd(&g_pool[curb*HID + lane*4+3], a0.w);
    atomicAdd(&g_pool[curb*HID + 128 + lane*4+0], a1.x);
    atomicAdd(&g_pool[curb*HID + 128 + lane*4+1], a1.y);
    atomicAdd(&g_pool[curb*HID + 128 + lane*4+2], a1.z);
    atomicAdd(&g_pool[curb*HID + 128 + lane*4+3], a1.w);
    if (lane == 0) atomicAdd(&g_bcnt[curb], cnt);
}

// ---------------- readout head ----------------
__global__ __launch_bounds__(256) void head_kernel(const float* __restrict__ w1,
                                                   const float* __restrict__ b1,
                                                   const float* __restrict__ w2,
                                                   const float* __restrict__ b2,
                                                   float* __restrict__ out) {
    __shared__ float p[BATCHB*HID];
    __shared__ float t[BATCHB*HID];
    int tid = threadIdx.x;
    for (int i = tid; i < BATCHB*HID; i += 256) {
        float c = fmaxf((float)g_bcnt[i / HID], 1.f);
        p[i] = g_pool[i] / c;
    }
    __syncthreads();
    {
        float acc[BATCHB];
        #pragma unroll
        for (int b = 0; b < BATCHB; b++) acc[b] = 0.f;
        for (int k = 0; k < HID; k++) {
            float w = w1[k*HID + tid];
            #pragma unroll
            for (int b = 0; b < BATCHB; b++) acc[b] += p[b*HID + k] * w;
        }
        #pragma unroll
        for (int b = 0; b < BATCHB; b++) {
            float v = acc[b] + b1[tid];
            t[b*HID + tid] = 0.5f * v * (1.f + erff(v * 0.70710678118654752f));
        }
    }
    __syncthreads();
    {
        float acc[BATCHB];
        #pragma unroll
        for (int b = 0; b < BATCHB; b++) acc[b] = 0.f;
        for (int k = 0; k < HID; k++) {
            float w = w2[k*HID + tid];
            #pragma unroll
            for (int b = 0; b < BATCHB; b++) acc[b] += t[b*HID + k] * w;
        }
        #pragma unroll
        for (int b = 0; b < BATCHB; b++) out[b*HID + tid] = acc[b] + b2[tid];
    }
}

// ---------------- launch ----------------
extern "C" void kernel_launch(void* const* d_in, const int* in_sizes, int n_in,
                              void* d_out, int out_size) {
    const float* x       = (const float*)d_in[0];
    const float* remb    = (const float*)d_in[1];
    const float* in_w    = (const float*)d_in[2];
    const float* in_b    = (const float*)d_in[3];
    const float* gat_w   = (const float*)d_in[4];
    const float* att_src = (const float*)d_in[5];
    const float* att_dst = (const float*)d_in[6];
    const float* gat_b   = (const float*)d_in[7];
    const float* ln_g    = (const float*)d_in[8];
    const float* ln_b    = (const float*)d_in[9];
    const float* ro_w1   = (const float*)d_in[10];
    const float* ro_b1   = (const float*)d_in[11];
    const float* ro_w2   = (const float*)d_in[12];
    const float* ro_b2   = (const float*)d_in[13];
    const int*   ei      = (const int*)d_in[14];
    const int*   batch   = (const int*)d_in[15];
    const int*   rid     = (const int*)d_in[16];
    float* out = (float*)d_out;

    dim3 gemm_grid((NN + 127)/128, HID/128);

    rates_kernel<<<1, 64>>>();                                                    // 0
    feats_kernel<<<(NN*48 + 255)/256, 256>>>(x, remb, rid);                       // 1
    zero_kernel<<<196, 256>>>();                                                  // 2
    // in-proj (K=192) — launch index 3 so ncu -s 5 captures it
    gemm_kernel<<<gemm_grid, 256>>>(in_w, in_b, nullptr, nullptr, NN, 192, 0);    // 3
    count_kernel<<<(TE + 255)/256, 256>>>(ei);                                    // 4
    scan1_kernel<<<196, 256>>>();                                                 // 5
    scan2_kernel<<<1, 256>>>(196);                                                // 6
    scan3_kernel<<<196, 256>>>();                                                 // 7
    fill_kernel<<<(TE + 255)/256, 256>>>(ei);                                     // 8

    for (int l = 0; l < 4; ++l) {
        gemm_kernel<<<gemm_grid, 256>>>(gat_w + (size_t)l*HID*HID, nullptr,
                                        att_src + l*256, att_dst + l*256, NN, HID, 1);
        aggregate_kernel<<<NN/8, 256>>>(gat_b + l*HID, ln_g + l*HID, ln_b + l*HID);
    }

    pool_kernel<<<196, 256>>>(batch);
    head_kernel<<<1, 256>>>(ro_w1, ro_b1, ro_w2, ro_b2, out);
}

// round 12
// speedup vs baseline: 1.9915x; 1.0627x over previous
#include <cuda_runtime.h>
#include <math.h>

#define NN 50000
#define NE 400000
#define TE 450000         // NE + NN self loops
#define HID 256
#define BATCHB 16

// ---------------- scratch ----------------
__device__ float g_h [(size_t)NN*HID];   // layer input / LN output
__device__ float g_hp[(size_t)NN*HID];   // h @ W (also feats buffer, N*192 < N*256)
__device__ float g_ssrc[NN*4];
__device__ float g_sdst[NN*4];
__device__ int   g_cnt[NN];
__device__ int   g_rowptr[NN+1];
__device__ int   g_cur[NN];
__device__ int   g_col[TE];
__device__ int   g_part[256];
__device__ float g_pool[BATCHB*HID];
__device__ int   g_bcnt[BATCHB];
__device__ float g_rates[64];

// ---------------- init ----------------
__global__ void zero_kernel() {
    int i = blockIdx.x*blockDim.x + threadIdx.x;
    if (i < NN) g_cnt[i] = 0;
    if (i < BATCHB*HID) g_pool[i] = 0.f;
    if (i < BATCHB) g_bcnt[i] = 0;
    if (i == 0) g_rowptr[NN] = TE;
}

__global__ void rates_kernel() {
    int j = threadIdx.x;
    if (j < 64) {
        double e = -(double)(2*(j>>1)) / 64.0;
        g_rates[j] = (float)pow(10000.0, e);
    }
}

// feats = [x | region_emb[rid] | posenc]  -> g_hp as [N,192], float4 granularity
__global__ void feats_kernel(const float* __restrict__ x,
                             const float* __restrict__ remb,
                             const int*   __restrict__ rid) {
    int idx = blockIdx.x*blockDim.x + threadIdx.x;
    if (idx >= NN*48) return;
    int n = idx / 48, q = idx - n*48;
    float4 v;
    if (q < 16)      v = ((const float4*)x)[(size_t)n*16 + q];
    else if (q < 32) v = ((const float4*)remb)[(size_t)rid[n]*16 + (q-16)];
    else {
        int j = (q - 32) * 4;
        float fn = (float)n;
        v.x = sinf(fn * g_rates[j+0]);
        v.y = cosf(fn * g_rates[j+1]);
        v.z = sinf(fn * g_rates[j+2]);
        v.w = cosf(fn * g_rates[j+3]);
    }
    ((float4*)g_hp)[(size_t)n*48 + q] = v;
}

// ---------------- CSR build (dst-major) ----------------
__global__ void count_kernel(const int* __restrict__ ei) {
    int i = blockIdx.x*blockDim.x + threadIdx.x;
    if (i >= TE) return;
    int dst = (i < NE) ? ei[NE + i] : (i - NE);
    atomicAdd(&g_cnt[dst], 1);
}

__global__ void scan1_kernel() {
    __shared__ int s[256];
    int tid = threadIdx.x;
    int i = blockIdx.x*256 + tid;
    int v = (i < NN) ? g_cnt[i] : 0;
    s[tid] = v; __syncthreads();
    #pragma unroll
    for (int off = 1; off < 256; off <<= 1) {
        int t = (tid >= off) ? s[tid-off] : 0;
        __syncthreads();
        s[tid] += t;
        __syncthreads();
    }
    if (i < NN) g_rowptr[i] = s[tid] - v;
    if (tid == 255) g_part[blockIdx.x] = s[255];
}

__global__ void scan2_kernel(int nb) {
    __shared__ int s[256];
    int tid = threadIdx.x;
    int v = (tid < nb) ? g_part[tid] : 0;
    s[tid] = v; __syncthreads();
    #pragma unroll
    for (int off = 1; off < 256; off <<= 1) {
        int t = (tid >= off) ? s[tid-off] : 0;
        __syncthreads();
        s[tid] += t;
        __syncthreads();
    }
    if (tid < nb) g_part[tid] = s[tid] - v;
}

__global__ void scan3_kernel() {
    int i = blockIdx.x*blockDim.x + threadIdx.x;
    if (i < NN) {
        int r = g_rowptr[i] + g_part[blockIdx.x];
        g_rowptr[i] = r;
        g_cur[i] = r;
    }
}

__global__ void fill_kernel(const int* __restrict__ ei) {
    int i = blockIdx.x*blockDim.x + threadIdx.x;
    if (i >= TE) return;
    int src, dst;
    if (i < NE) { src = ei[i]; dst = ei[NE+i]; }
    else        { src = dst = i - NE; }
    int pos = atomicAdd(&g_cur[dst], 1);
    g_col[pos] = src;
}

// ---------------- GEMM: C[M,256] = A[M,K] @ W[K,256] (+bias) + fused scores ----------------
__device__ __forceinline__ void ffma2(unsigned long long& d,
                                      unsigned long long a,
                                      unsigned long long b) {
    asm volatile("fma.rn.f32x2 %0, %1, %2, %0;" : "+l"(d) : "l"(a), "l"(b));
}
__device__ __forceinline__ void cp16(void* smem_dst, const void* gsrc, int src_bytes) {
    unsigned saddr = (unsigned)__cvta_generic_to_shared(smem_dst);
    asm volatile("cp.async.cg.shared.global [%0], [%1], 16, %2;"
                 :: "r"(saddr), "l"(gsrc), "r"(src_bytes));
}
__device__ __forceinline__ void cp_commit() { asm volatile("cp.async.commit_group;"); }
__device__ __forceinline__ void cp_wait1()  { asm volatile("cp.async.wait_group 1;"); }
__device__ __forceinline__ void cp_wait0()  { asm volatile("cp.async.wait_group 0;"); }

// BM=128 BN=128 BK=16, 256 threads, 8x8 microtile, FFMA2, 3-stage pipeline, 1 barrier/tile.
// Thread's 8 columns: {tx*4..+3} and {64+tx*4..+3} -> both B LDS.128 conflict-free
// (16B lane stride) instead of the 2-phase-doubling 32B stride.
__global__ __launch_bounds__(256, 2) void gemm_kernel(const float* __restrict__ W,
                                                      const float* __restrict__ bias,
                                                      const float* __restrict__ asrc,
                                                      const float* __restrict__ adst,
                                                      int M, int K, int a_is_h) {
    const float* __restrict__ A = a_is_h ? g_h : g_hp;
    float* __restrict__ C       = a_is_h ? g_hp : g_h;

    __shared__ float As[3][128][16];
    __shared__ float Bs[3][16][128];

    int tid = threadIdx.x;
    int bm = blockIdx.x * 128;
    int bn = blockIdx.y * 128;
    int tx = tid & 15;
    int ty = tid >> 4;

    unsigned long long acc[8][4];   // acc[i][0..1]: cols tx*4..+3 ; acc[i][2..3]: cols 64+tx*4..+3
    #pragma unroll
    for (int i = 0; i < 8; i++)
        #pragma unroll
        for (int j = 0; j < 4; j++) acc[i][j] = 0ull;

    int a_r = tid >> 2;
    int a_c = (tid & 3) * 4;
    int b_k = tid >> 4;
    int b_c = (tid & 15) * 4;

    int nk = K >> 4;

    #pragma unroll
    for (int st = 0; st < 2; st++) {
        int k0 = st << 4;
        #pragma unroll
        for (int r = 0; r < 2; r++) {
            int row = a_r + r*64;
            int grow = bm + row;
            const float* p = (grow < M) ? (A + (size_t)grow*K + k0 + a_c) : A;
            cp16(&As[st][row][a_c], p, (grow < M) ? 16 : 0);
        }
        #pragma unroll
        for (int r = 0; r < 2; r++) {
            int col = b_c + r*64;
            cp16(&Bs[st][b_k][col], W + (size_t)(k0 + b_k)*HID + bn + col, 16);
        }
        cp_commit();
    }

    int cur = 0, nxt = 2;
    for (int it = 0; it < nk; ++it) {
        if (it + 1 < nk) cp_wait1(); else cp_wait0();
        __syncthreads();

        if (it + 2 < nk) {
            int k0 = (it + 2) << 4;
            #pragma unroll
            for (int r = 0; r < 2; r++) {
                int row = a_r + r*64;
                int grow = bm + row;
                const float* p = (grow < M) ? (A + (size_t)grow*K + k0 + a_c) : A;
                cp16(&As[nxt][row][a_c], p, (grow < M) ? 16 : 0);
            }
            #pragma unroll
            for (int r = 0; r < 2; r++) {
                int col = b_c + r*64;
                cp16(&Bs[nxt][b_k][col], W + (size_t)(k0 + b_k)*HID + bn + col, 16);
            }
            cp_commit();
        }

        #pragma unroll
        for (int kq = 0; kq < 16; kq += 4) {
            float4 a4[8];
            #pragma unroll
            for (int i = 0; i < 8; i++)
                a4[i] = *(const float4*)(&As[cur][ty*8+i][kq]);
            #pragma unroll
            for (int kk = 0; kk < 4; ++kk) {
                ulonglong2 bA = *(const ulonglong2*)(&Bs[cur][kq+kk][tx*4]);        // cols tx*4..+3
                ulonglong2 bB = *(const ulonglong2*)(&Bs[cur][kq+kk][64 + tx*4]);   // cols 64+tx*4..+3
                #pragma unroll
                for (int i = 0; i < 8; i++) {
                    float a = (kk == 0) ? a4[i].x : (kk == 1) ? a4[i].y
                            : (kk == 2) ? a4[i].z : a4[i].w;
                    unsigned long long a2;
                    asm("mov.b64 %0, {%1, %1};" : "=l"(a2) : "f"(a));
                    ffma2(acc[i][0], a2, bA.x);
                    ffma2(acc[i][1], a2, bA.y);
                    ffma2(acc[i][2], a2, bB.x);
                    ffma2(acc[i][3], a2, bB.y);
                }
            }
        }
        cur = (cur == 2) ? 0 : cur + 1;
        nxt = (nxt == 2) ? 0 : nxt + 1;
    }

    float cv[8][8];   // [i][0..3] -> cols bn+tx*4..+3 ; [i][4..7] -> cols bn+64+tx*4..+3
    #pragma unroll
    for (int i = 0; i < 8; i++) {
        float2 p0 = *(float2*)&acc[i][0];
        float2 p1 = *(float2*)&acc[i][1];
        float2 p2 = *(float2*)&acc[i][2];
        float2 p3 = *(float2*)&acc[i][3];
        cv[i][0]=p0.x; cv[i][1]=p0.y; cv[i][2]=p1.x; cv[i][3]=p1.y;
        cv[i][4]=p2.x; cv[i][5]=p2.y; cv[i][6]=p3.x; cv[i][7]=p3.y;
    }
    int c0 = bn + tx*4;
    int c1 = bn + 64 + tx*4;
    if (bias) {
        float4 t0 = *(const float4*)(bias + c0);
        float4 t1 = *(const float4*)(bias + c1);
        #pragma unroll
        for (int i = 0; i < 8; i++) {
            cv[i][0]+=t0.x; cv[i][1]+=t0.y; cv[i][2]+=t0.z; cv[i][3]+=t0.w;
            cv[i][4]+=t1.x; cv[i][5]+=t1.y; cv[i][6]+=t1.z; cv[i][7]+=t1.w;
        }
    }
    #pragma unroll
    for (int i = 0; i < 8; i++) {
        int row = bm + ty*8 + i;
        if (row < M) {
            *(float4*)(C + (size_t)row*HID + c0) = make_float4(cv[i][0],cv[i][1],cv[i][2],cv[i][3]);
            *(float4*)(C + (size_t)row*HID + c1) = make_float4(cv[i][4],cv[i][5],cv[i][6],cv[i][7]);
        }
    }

    // fused scores: head0 = bn/64 (cols 0..63 of bn half), head1 = head0+1
    if (asrc) {
        int head0 = bn >> 6;
        int head1 = head0 + 1;
        float av0[4], av1[4], dv0[4], dv1[4];
        #pragma unroll
        for (int j = 0; j < 4; j++) {
            av0[j] = asrc[head0*64 + tx*4 + j];
            av1[j] = asrc[head1*64 + tx*4 + j];
            dv0[j] = adst[head0*64 + tx*4 + j];
            dv1[j] = adst[head1*64 + tx*4 + j];
        }
        #pragma unroll
        for (int i = 0; i < 8; i++) {
            float ps0 = 0.f, pd0 = 0.f, ps1 = 0.f, pd1 = 0.f;
            #pragma unroll
            for (int j = 0; j < 4; j++) {
                ps0 += cv[i][j]   * av0[j];
                pd0 += cv[i][j]   * dv0[j];
                ps1 += cv[i][4+j] * av1[j];
                pd1 += cv[i][4+j] * dv1[j];
            }
            #pragma unroll
            for (int off = 8; off; off >>= 1) {
                ps0 += __shfl_xor_sync(0xffffffffu, ps0, off, 16);
                pd0 += __shfl_xor_sync(0xffffffffu, pd0, off, 16);
                ps1 += __shfl_xor_sync(0xffffffffu, ps1, off, 16);
                pd1 += __shfl_xor_sync(0xffffffffu, pd1, off, 16);
            }
            int row = bm + ty*8 + i;
            if (tx == 0 && row < M) {
                g_ssrc[(size_t)row*4 + head0] = ps0;
                g_ssrc[(size_t)row*4 + head1] = ps1;
                g_sdst[(size_t)row*4 + head0] = pd0;
                g_sdst[(size_t)row*4 + head1] = pd1;
            }
        }
    }
}

// ---------------- aggregation + bias + relu + layernorm: one warp per dst ----------------
// Single pass (scores bounded; softmax shift-invariant -> no max pass).
__global__ void aggregate_kernel(const float* __restrict__ bias,
                                 const float* __restrict__ lng,
                                 const float* __restrict__ lnb) {
    int warp = (blockIdx.x*blockDim.x + threadIdx.x) >> 5;
    int lane = threadIdx.x & 31;
    if (warp >= NN) return;
    int n = warp;
    int start = g_rowptr[n], end = g_rowptr[n+1];

    float4 sd4 = *(const float4*)(g_sdst + (size_t)n*4);
    bool lo = (lane < 16);
    float sdh0 = lo ? sd4.x : sd4.y;
    float sdh1 = lo ? sd4.z : sd4.w;

    float ax = 0.f, ay = 0.f, az = 0.f, aw = 0.f;
    float bx = 0.f, by = 0.f, bz2 = 0.f, bw = 0.f;
    float den0 = 0.f, den1 = 0.f;
    for (int i = start; i < end; ++i) {
        int s = g_col[i];
        float4 ss = *(const float4*)(g_ssrc + (size_t)s*4);
        float e0 = (lo ? ss.x : ss.y) + sdh0; e0 = e0 > 0.f ? e0 : 0.2f*e0;
        float e1 = (lo ? ss.z : ss.w) + sdh1; e1 = e1 > 0.f ? e1 : 0.2f*e1;
        float w0 = __expf(e0);
        float w1 = __expf(e1);
        den0 += w0; den1 += w1;
        const float4* row = (const float4*)(g_hp + (size_t)s*HID);
        float4 v0 = row[lane], v1 = row[lane+32];
        ax += w0*v0.x; ay += w0*v0.y; az += w0*v0.z; aw += w0*v0.w;
        bx += w1*v1.x; by += w1*v1.y; bz2 += w1*v1.z; bw += w1*v1.w;
    }
    float inv0 = 1.f/den0, inv1 = 1.f/den1;

    int c0 = lane*4, c1 = 128 + lane*4;
    float4 bb0 = *(const float4*)(bias + c0);
    float4 bb1 = *(const float4*)(bias + c1);
    float vals[8];
    vals[0] = fmaxf(0.f, ax*inv0 + bb0.x);
    vals[1] = fmaxf(0.f, ay*inv0 + bb0.y);
    vals[2] = fmaxf(0.f, az*inv0 + bb0.z);
    vals[3] = fmaxf(0.f, aw*inv0 + bb0.w);
    vals[4] = fmaxf(0.f, bx*inv1 + bb1.x);
    vals[5] = fmaxf(0.f, by*inv1 + bb1.y);
    vals[6] = fmaxf(0.f, bz2*inv1 + bb1.z);
    vals[7] = fmaxf(0.f, bw*inv1 + bb1.w);

    float lsum = 0.f;
    #pragma unroll
    for (int j = 0; j < 8; j++) lsum += vals[j];
    #pragma unroll
    for (int off = 16; off; off >>= 1) lsum += __shfl_xor_sync(0xffffffffu, lsum, off);
    float mu = lsum * (1.f/256.f);
    float lsq = 0.f;
    #pragma unroll
    for (int j = 0; j < 8; j++) { float d = vals[j]-mu; lsq += d*d; }
    #pragma unroll
    for (int off = 16; off; off >>= 1) lsq += __shfl_xor_sync(0xffffffffu, lsq, off);
    float rstd = rsqrtf(lsq * (1.f/256.f) + 1e-5f);

    float4 gg0 = *(const float4*)(lng + c0);
    float4 gg1 = *(const float4*)(lng + c1);
    float4 lb0 = *(const float4*)(lnb + c0);
    float4 lb1 = *(const float4*)(lnb + c1);
    float4 o0, o1;
    o0.x = (vals[0]-mu)*rstd*gg0.x + lb0.x;
    o0.y = (vals[1]-mu)*rstd*gg0.y + lb0.y;
    o0.z = (vals[2]-mu)*rstd*gg0.z + lb0.z;
    o0.w = (vals[3]-mu)*rstd*gg0.w + lb0.w;
    o1.x = (vals[4]-mu)*rstd*gg1.x + lb1.x;
    o1.y = (vals[5]-mu)*rstd*gg1.y + lb1.y;
    o1.z = (vals[6]-mu)*rstd*gg1.z + lb1.z;
    o1.w = (vals[7]-mu)*rstd*gg1.w + lb1.w;
    *(float4*)(g_h + (size_t)n*HID + c0) = o0;
    *(float4*)(g_h + (size_t)n*HID + c1) = o1;
}

// ---------------- pooling ----------------
__global__ void pool_kernel(const int* __restrict__ batch) {
    int gw = (blockIdx.x*blockDim.x + threadIdx.x) >> 5;
    int lane = threadIdx.x & 31;
    int n0 = gw * 32;
    if (n0 >= NN) return;
    int nend = n0 + 32; if (nend > NN) nend = NN;

    float4 a0 = make_float4(0,0,0,0), a1 = make_float4(0,0,0,0);
    int curb = batch[n0];
    int cnt = 0;
    for (int n = n0; n < nend; ++n) {
        int b = batch[n];
        if (b != curb) {
            atomicAdd(&g_pool[curb*HID + lane*4+0], a0.x);
            atomicAdd(&g_pool[curb*HID + lane*4+1], a0.y);
            atomicAdd(&g_pool[curb*HID + lane*4+2], a0.z);
            atomicAdd(&g_pool[curb*HID + lane*4+3], a0.w);
            atomicAdd(&g_pool[curb*HID + 128 + lane*4+0], a1.x);
            atomicAdd(&g_pool[curb*HID + 128 + lane*4+1], a1.y);
            atomicAdd(&g_pool[curb*HID + 128 + lane*4+2], a1.z);
            atomicAdd(&g_pool[curb*HID + 128 + lane*4+3], a1.w);
            if (lane == 0) atomicAdd(&g_bcnt[curb], cnt);
            a0 = make_float4(0,0,0,0); a1 = make_float4(0,0,0,0);
            cnt = 0; curb = b;
        }
        const float4* row = (const float4*)(g_h + (size_t)n*HID);
        float4 v0 = row[lane], v1 = row[lane+32];
        a0.x += v0.x; a0.y += v0.y; a0.z += v0.z; a0.w += v0.w;
        a1.x += v1.x; a1.y += v1.y; a1.z += v1.z; a1.w += v1.w;
        cnt++;
    }
    atomicAdd(&g_pool[curb*HID + lane*4+0], a0.x);
    atomicAdd(&g_pool[curb*HID + lane*4+1], a0.y);
    atomicAdd(&g_pool[curb*HID + lane*4+2], a0.z);
    atomicAdd(&g_pool[curb*HID + lane*4+3], a0.w);
    atomicAdd(&g_pool[curb*HID + 128 + lane*4+0], a1.x);
    atomicAdd(&g_pool[curb*HID + 128 + lane*4+1], a1.y);
    atomicAdd(&g_pool[curb*HID + 128 + lane*4+2], a1.z);
    atomicAdd(&g_pool[curb*HID + 128 + lane*4+3], a1.w);
    if (lane == 0) atomicAdd(&g_bcnt[curb], cnt);
}

// ---------------- readout head ----------------
__global__ __launch_bounds__(256) void head_kernel(const float* __restrict__ w1,
                                                   const float* __restrict__ b1,
                                                   const float* __restrict__ w2,
                                                   const float* __restrict__ b2,
                                                   float* __restrict__ out) {
    __shared__ float p[BATCHB*HID];
    __shared__ float t[BATCHB*HID];
    int tid = threadIdx.x;
    for (int i = tid; i < BATCHB*HID; i += 256) {
        float c = fmaxf((float)g_bcnt[i / HID], 1.f);
        p[i] = g_pool[i] / c;
    }
    __syncthreads();
    {
        float acc[BATCHB];
        #pragma unroll
        for (int b = 0; b < BATCHB; b++) acc[b] = 0.f;
        for (int k = 0; k < HID; k++) {
            float w = w1[k*HID + tid];
            #pragma unroll
            for (int b = 0; b < BATCHB; b++) acc[b] += p[b*HID + k] * w;
        }
        #pragma unroll
        for (int b = 0; b < BATCHB; b++) {
            float v = acc[b] + b1[tid];
            t[b*HID + tid] = 0.5f * v * (1.f + erff(v * 0.70710678118654752f));
        }
    }
    __syncthreads();
    {
        float acc[BATCHB];
        #pragma unroll
        for (int b = 0; b < BATCHB; b++) acc[b] = 0.f;
        for (int k = 0; k < HID; k++) {
            float w = w2[k*HID + tid];
            #pragma unroll
            for (int b = 0; b < BATCHB; b++) acc[b] += t[b*HID + k] * w;
        }
        #pragma unroll
        for (int b = 0; b < BATCHB; b++) out[b*HID + tid] = acc[b] + b2[tid];
    }
}

// ---------------- launch ----------------
extern "C" void kernel_launch(void* const* d_in, const int* in_sizes, int n_in,
                              void* d_out, int out_size) {
    const float* x       = (const float*)d_in[0];
    const float* remb    = (const float*)d_in[1];
    const float* in_w    = (const float*)d_in[2];
    const float* in_b    = (const float*)d_in[3];
    const float* gat_w   = (const float*)d_in[4];
    const float* att_src = (const float*)d_in[5];
    const float* att_dst = (const float*)d_in[6];
    const float* gat_b   = (const float*)d_in[7];
    const float* ln_g    = (const float*)d_in[8];
    const float* ln_b    = (const float*)d_in[9];
    const float* ro_w1   = (const float*)d_in[10];
    const float* ro_b1   = (const float*)d_in[11];
    const float* ro_w2   = (const float*)d_in[12];
    const float* ro_b2   = (const float*)d_in[13];
    const int*   ei      = (const int*)d_in[14];
    const int*   batch   = (const int*)d_in[15];
    const int*   rid     = (const int*)d_in[16];
    float* out = (float*)d_out;

    dim3 gemm_grid((NN + 127)/128, HID/128);

    rates_kernel<<<1, 64>>>();                                                    // 0
    feats_kernel<<<(NN*48 + 255)/256, 256>>>(x, remb, rid);                       // 1
    // in-proj (K=192)
    gemm_kernel<<<gemm_grid, 256>>>(in_w, in_b, nullptr, nullptr, NN, 192, 0);    // 2
    // layer-0 GEMM (K=256 + score epilogue) — launch index 3, profiled
    gemm_kernel<<<gemm_grid, 256>>>(gat_w, nullptr, att_src, att_dst, NN, HID, 1);// 3
    // CSR build (only needed by aggregate)
    zero_kernel<<<196, 256>>>();                                                  // 4
    count_kernel<<<(TE + 255)/256, 256>>>(ei);                                    // 5
    scan1_kernel<<<196, 256>>>();                                                 // 6
    scan2_kernel<<<1, 256>>>(196);                                                // 7
    scan3_kernel<<<196, 256>>>();                                                 // 8
    fill_kernel<<<(TE + 255)/256, 256>>>(ei);                                     // 9
    aggregate_kernel<<<NN/8, 256>>>(gat_b, ln_g, ln_b);                           // 10

    for (int l = 1; l < 4; ++l) {
        gemm_kernel<<<gemm_grid, 256>>>(gat_w + (size_t)l*HID*HID, nullptr,
                                        att_src + l*256, att_dst + l*256, NN, HID, 1);
        aggregate_kernel<<<NN/8, 256>>>(gat_b + l*HID, ln_g + l*HID, ln_b + l*HID);
    }

    pool_kernel<<<196, 256>>>(batch);
    head_kernel<<<1, 256>>>(ro_w1, ro_b1, ro_w2, ro_b2, out);
}